// round 10
// baseline (speedup 1.0000x reference)
#include <cuda_runtime.h>
#include <cuda_fp16.h>
#include <cstdint>
#include <math.h>

// ============================================================================
// Time2Vec:  out[:, :1024] = w*x + p
//            out[:, 1024:] = sine_w*sin(x@W + P) + cosine_w*cos(x@W + P)
// GEMM via mma.sync.m16n8k16 fp16 2-way-split (3 MMAs, fp32 accum).
// (tcgen05 is unavailable: harness ptxas targets sm_103, not sm_103a.)
// ============================================================================

#define F       1024
#define BATCH   65536
#define BM      128
#define BN      128
#define BK      32
#define NKC     (F / BK)            // 32
#define THREADS 256

#define STAGE_BYTES 32768           // A: 16KB (128 rows x 128B), B: 16KB
#define A_OFF       0
#define B_OFF       16384
#define SMEM_TOTAL  (2 * STAGE_BYTES)

// Pre-split W (row-major [k][n], fp16 hi/lo)
__device__ __half g_Wh[(size_t)F * F];
__device__ __half g_Wl[(size_t)F * F];

// ---------------------------------------------------------------------------
// helpers
// ---------------------------------------------------------------------------
__device__ __forceinline__ uint32_t smem_u32(const void* p) {
    uint32_t a;
    asm("{ .reg .u64 t; cvta.to.shared.u64 t, %1; cvt.u32.u64 %0, t; }"
        : "=r"(a) : "l"(p));
    return a;
}

#define SWZ(o) ((uint32_t)(o) ^ ((((uint32_t)(o)) >> 3) & 0x70))

__device__ __forceinline__ void ldsm_x4(uint32_t* r, uint32_t addr) {
    asm volatile(
        "ldmatrix.sync.aligned.m8n8.x4.shared.b16 {%0,%1,%2,%3}, [%4];"
        : "=r"(r[0]), "=r"(r[1]), "=r"(r[2]), "=r"(r[3]) : "r"(addr));
}
__device__ __forceinline__ void ldsm_x4_t(uint32_t* r, uint32_t addr) {
    asm volatile(
        "ldmatrix.sync.aligned.m8n8.x4.trans.shared.b16 {%0,%1,%2,%3}, [%4];"
        : "=r"(r[0]), "=r"(r[1]), "=r"(r[2]), "=r"(r[3]) : "r"(addr));
}
__device__ __forceinline__ void mma16816(float* c, const uint32_t* a,
                                         const uint32_t* b) {
    asm volatile(
        "mma.sync.aligned.m16n8k16.row.col.f32.f16.f16.f32 "
        "{%0,%1,%2,%3}, {%4,%5,%6,%7}, {%8,%9}, {%0,%1,%2,%3};"
        : "+f"(c[0]), "+f"(c[1]), "+f"(c[2]), "+f"(c[3])
        : "r"(a[0]), "r"(a[1]), "r"(a[2]), "r"(a[3]), "r"(b[0]), "r"(b[1]));
}
__device__ __forceinline__ void cp_async16(uint32_t d, const void* g) {
    asm volatile("cp.async.cg.shared.global [%0], [%1], 16;"
                 :: "r"(d), "l"(g) : "memory");
}
#define CP_COMMIT() asm volatile("cp.async.commit_group;" ::: "memory")
#define CP_WAIT0()  asm volatile("cp.async.wait_group 0;" ::: "memory")

__device__ __forceinline__ uint32_t pack_h2(__half a, __half b) {
    __half2 h = __halves2half2(a, b);
    return *reinterpret_cast<uint32_t*>(&h);
}

// ---------------------------------------------------------------------------
// Kernel 1: split W -> g_Wh/g_Wl (same [k][n] layout)
// ---------------------------------------------------------------------------
__global__ void wsplit_kernel(const float* __restrict__ W) {
    const size_t i = ((size_t)blockIdx.x * 256 + threadIdx.x) * 4;
    const float4 v = *(const float4*)(W + i);
    const __half h0 = __float2half_rn(v.x), h1 = __float2half_rn(v.y);
    const __half h2 = __float2half_rn(v.z), h3 = __float2half_rn(v.w);
    const __half l0 = __float2half_rn(v.x - __half2float(h0));
    const __half l1 = __float2half_rn(v.y - __half2float(h1));
    const __half l2 = __float2half_rn(v.z - __half2float(h2));
    const __half l3 = __float2half_rn(v.w - __half2float(h3));
    *(uint2*)(g_Wh + i) = make_uint2(pack_h2(h0, h1), pack_h2(h2, h3));
    *(uint2*)(g_Wl + i) = make_uint2(pack_h2(l0, l1), pack_h2(l2, l3));
}

// ---------------------------------------------------------------------------
// Kernel 2: pipelined split-fp16 HMMA GEMM + fused Time2Vec epilogue
// ---------------------------------------------------------------------------
__global__ __launch_bounds__(THREADS, 1)
void t2v_kernel(const float* __restrict__ x,
                const float* __restrict__ P,
                const float* __restrict__ w_p,
                const float* __restrict__ p_p,
                const float* __restrict__ sw_p,
                const float* __restrict__ cw_p,
                float* __restrict__ out) {
    extern __shared__ char smem[];
    const uint32_t sbase = smem_u32(smem);
    const int tid = threadIdx.x;
    const int lane = tid & 31, wid = tid >> 5;
    const int warp_m = wid & 3, warp_n = wid >> 2;     // 4 x 2 warps
    const int bm = blockIdx.x >> 3, bn = blockIdx.x & 7;
    const int m0 = bm * BM, n0 = bn * BN;

    const float w_s = __ldg(w_p), p_s = __ldg(p_p);
    const float sw = __ldg(sw_p), cw = __ldg(cw_p);

    // ---- per-thread x-load / STS-A geometry ----
    const int xrow = tid >> 1;                         // 0..127
    const int xch  = (tid & 1) * 16;                   // col half (fp32 elems)
    const float* xg = x + (size_t)(m0 + xrow) * F + xch;
    float* og = out + (size_t)(m0 + xrow) * (2 * F) + xch;
    const uint32_t xswz = ((uint32_t)(xrow) & 7u) << 4;  // SW128 XOR for row
    const uint32_t sts_base = (uint32_t)(xrow * 128 + (tid & 1) * 32);

    // ---- per-thread cp.async(B) geometry (4 x 16B per stage) ----
    uint32_t b_dst[4];
    const __half* b_src[4];
    {
#pragma unroll
        for (int i = 0; i < 4; i++) {
            const int idx = tid + i * 256;             // 0..1023
            const int hl = idx >> 9;                   // 0=hi, 1=lo
            const int rem = idx & 511;
            const int r = rem >> 3;                    // 0..63 = nh*32 + k
            const int c = rem & 7;                     // 16B chunk in row
            const int nh = r >> 5, kk = r & 31;
            b_dst[i] = SWZ((hl * 64 + r) * 128 + c * 16);
            b_src[i] = (hl ? g_Wl : g_Wh) + (size_t)kk * F + n0 + nh * 64 + c * 8;
        }
    }

    // ---- per-lane ldmatrix geometry ----
    const uint32_t abase =
        (uint32_t)((warp_m * 32 + (lane & 15)) * 128 + (lane >> 4) * 16);
    const uint32_t aswz = ((uint32_t)(lane) & 7u) << 4;
    const uint32_t bbase =
        (uint32_t)((warp_n * 32 + (lane & 15)) * 128 + (lane >> 4) * 16);
    const uint32_t bswz = ((uint32_t)(lane) & 7u) << 4;

    float acc[2][8][4];
#pragma unroll
    for (int mt = 0; mt < 2; mt++)
#pragma unroll
        for (int nt = 0; nt < 8; nt++)
#pragma unroll
            for (int q = 0; q < 4; q++) acc[mt][nt][q] = 0.0f;

    // ---- prologue: x(0) regs + B(0) cp.async ----
    float4 xr[4];
#pragma unroll
    for (int q = 0; q < 4; q++) xr[q] = __ldg((const float4*)(xg + q * 4));
    {
        const uint32_t sB = sbase + B_OFF;             // stage 0
#pragma unroll
        for (int i = 0; i < 4; i++) cp_async16(sB + b_dst[i], b_src[i]);
        CP_COMMIT();
    }

    // ---- mainloop ----
    for (int kc = 0; kc < NKC; kc++) {
        const int s = kc & 1;
        const uint32_t sA = sbase + s * STAGE_BYTES + A_OFF;
        const uint32_t sB = sbase + s * STAGE_BYTES + B_OFF;
        char* sAc = smem + s * STAGE_BYTES + A_OFF;

        CP_WAIT0();   // B(kc) landed

        // convert x(kc) -> Ah|Al rows; emit linear half from bn==0 CTAs
#pragma unroll
        for (int q = 0; q < 4; q++) {
            const float4 v = xr[q];
            const __half h0 = __float2half_rn(v.x), h1 = __float2half_rn(v.y);
            const __half h2 = __float2half_rn(v.z), h3 = __float2half_rn(v.w);
            const __half l0 = __float2half_rn(v.x - __half2float(h0));
            const __half l1 = __float2half_rn(v.y - __half2float(h1));
            const __half l2 = __float2half_rn(v.z - __half2float(h2));
            const __half l3 = __float2half_rn(v.w - __half2float(h3));
            const uint32_t oh = sts_base + q * 8;
            *(uint2*)(sAc + (oh ^ xswz)) =
                make_uint2(pack_h2(h0, h1), pack_h2(h2, h3));
            *(uint2*)(sAc + ((oh + 64) ^ xswz)) =
                make_uint2(pack_h2(l0, l1), pack_h2(l2, l3));
            if (bn == 0) {
                float4 o;
                o.x = w_s * v.x + p_s; o.y = w_s * v.y + p_s;
                o.z = w_s * v.z + p_s; o.w = w_s * v.w + p_s;
                *(float4*)(og + kc * 32 + q * 4) = o;
            }
        }
        __syncthreads();   // A+B of chunk kc visible; prior-chunk reads done

        if (kc < NKC - 1) {
            // prefetch x(kc+1) and B(kc+1) under the MMA shadow
#pragma unroll
            for (int q = 0; q < 4; q++)
                xr[q] = __ldg((const float4*)(xg + (kc + 1) * 32 + q * 4));
            const uint32_t sBn = sbase + (s ^ 1) * STAGE_BYTES + B_OFF;
            const size_t kadv = (size_t)(kc + 1) * 32 * F;
#pragma unroll
            for (int i = 0; i < 4; i++)
                cp_async16(sBn + b_dst[i], b_src[i] + kadv);
            CP_COMMIT();
        }

        // ---- MMAs over stage s ----
#pragma unroll
        for (int ks = 0; ks < 2; ks++) {
            uint32_t ah[2][4], al[2][4], bh[8][2], bl[8][2];
#pragma unroll
            for (int mt = 0; mt < 2; mt++) {
                ldsm_x4(ah[mt], sA + ((abase + mt * 2048 + ks * 32) ^ aswz));
                ldsm_x4(al[mt],
                        sA + ((abase + mt * 2048 + 64 + ks * 32) ^ aswz));
            }
#pragma unroll
            for (int np = 0; np < 4; np++) {
                uint32_t t4[4];
                ldsm_x4_t(t4, sB + ((bbase + ks * 2048 + np * 32) ^ bswz));
                bh[np * 2][0] = t4[0]; bh[np * 2][1] = t4[1];
                bh[np * 2 + 1][0] = t4[2]; bh[np * 2 + 1][1] = t4[3];
                ldsm_x4_t(t4,
                          sB + ((bbase + 8192 + ks * 2048 + np * 32) ^ bswz));
                bl[np * 2][0] = t4[0]; bl[np * 2][1] = t4[1];
                bl[np * 2 + 1][0] = t4[2]; bl[np * 2 + 1][1] = t4[3];
            }
#pragma unroll
            for (int mt = 0; mt < 2; mt++)
#pragma unroll
                for (int nt = 0; nt < 8; nt++) {
                    mma16816(acc[mt][nt], ah[mt], bh[nt]);
                    mma16816(acc[mt][nt], ah[mt], bl[nt]);
                    mma16816(acc[mt][nt], al[mt], bh[nt]);
                }
        }
    }

    // ---- epilogue: z = acc + P[n]; periodic = sw*sin(z)+cw*cos(z) ----
    const int gid = lane >> 2, tig = lane & 3;
#pragma unroll
    for (int nt = 0; nt < 8; nt++) {
        const int n = n0 + warp_n * 64 + nt * 8 + tig * 2;
        const float P0 = __ldg(P + n), P1 = __ldg(P + n + 1);
#pragma unroll
        for (int mt = 0; mt < 2; mt++) {
            const int mrow = m0 + warp_m * 32 + mt * 16 + gid;
            float s0, c0, s1, c1;
            __sincosf(acc[mt][nt][0] + P0, &s0, &c0);
            __sincosf(acc[mt][nt][1] + P1, &s1, &c1);
            *(float2*)(out + (size_t)mrow * (2 * F) + F + n) =
                make_float2(sw * s0 + cw * c0, sw * s1 + cw * c1);
            __sincosf(acc[mt][nt][2] + P0, &s0, &c0);
            __sincosf(acc[mt][nt][3] + P1, &s1, &c1);
            *(float2*)(out + (size_t)(mrow + 8) * (2 * F) + F + n) =
                make_float2(sw * s0 + cw * c0, sw * s1 + cw * c1);
        }
    }
}

// ---------------------------------------------------------------------------
extern "C" void kernel_launch(void* const* d_in, const int* in_sizes, int n_in,
                              void* d_out, int out_size) {
    (void)in_sizes; (void)n_in; (void)out_size;
    const float* x  = (const float*)d_in[0];
    const float* W  = (const float*)d_in[1];
    const float* P  = (const float*)d_in[2];
    const float* w  = (const float*)d_in[3];
    const float* p  = (const float*)d_in[4];
    const float* sw = (const float*)d_in[5];
    const float* cw = (const float*)d_in[6];
    float* out = (float*)d_out;

    cudaFuncSetAttribute(t2v_kernel,
                         cudaFuncAttributeMaxDynamicSharedMemorySize,
                         SMEM_TOTAL);

    wsplit_kernel<<<(F * F) / (256 * 4), 256>>>(W);
    t2v_kernel<<<(BATCH / BM) * (F / BN), THREADS, SMEM_TOTAL>>>(
        x, P, w, p, sw, cw, out);
}

// round 11
// speedup vs baseline: 1.2330x; 1.2330x over previous
#include <cuda_runtime.h>
#include <cuda_fp16.h>
#include <cstdint>
#include <math.h>

// ============================================================================
// Time2Vec:  out[:, :1024] = w*x + p
//            out[:, 1024:] = sine_w*sin(x@W + P) + cosine_w*cos(x@W + P)
// GEMM via mma.sync.m16n8k16 fp16 2-way-split (3 MMAs, fp32 accum).
// R11: 64x64 warp tiles (2x2 warps, 128 thr) to halve ldmatrix traffic;
//      2 CTAs/SM for latency hiding. (tcgen05 unavailable: ptxas -> sm_103.)
// ============================================================================

#define F       1024
#define BATCH   65536
#define BM      128
#define BN      128
#define BK      32
#define NKC     (F / BK)            // 32
#define THREADS 128

#define STAGE_BYTES 32768           // A: 16KB (128 rows x 128B), B: 16KB
#define A_OFF       0
#define B_OFF       16384
#define SMEM_TOTAL  (2 * STAGE_BYTES)   // 64 KB -> 2 CTAs/SM

// Pre-split W (row-major [k][n], fp16 hi/lo)
__device__ __half g_Wh[(size_t)F * F];
__device__ __half g_Wl[(size_t)F * F];

// ---------------------------------------------------------------------------
// helpers
// ---------------------------------------------------------------------------
__device__ __forceinline__ uint32_t smem_u32(const void* p) {
    uint32_t a;
    asm("{ .reg .u64 t; cvta.to.shared.u64 t, %1; cvt.u32.u64 %0, t; }"
        : "=r"(a) : "l"(p));
    return a;
}

#define SWZ(o) ((uint32_t)(o) ^ ((((uint32_t)(o)) >> 3) & 0x70))

__device__ __forceinline__ void ldsm_x4(uint32_t* r, uint32_t addr) {
    asm volatile(
        "ldmatrix.sync.aligned.m8n8.x4.shared.b16 {%0,%1,%2,%3}, [%4];"
        : "=r"(r[0]), "=r"(r[1]), "=r"(r[2]), "=r"(r[3]) : "r"(addr));
}
__device__ __forceinline__ void ldsm_x4_t(uint32_t* r, uint32_t addr) {
    asm volatile(
        "ldmatrix.sync.aligned.m8n8.x4.trans.shared.b16 {%0,%1,%2,%3}, [%4];"
        : "=r"(r[0]), "=r"(r[1]), "=r"(r[2]), "=r"(r[3]) : "r"(addr));
}
__device__ __forceinline__ void mma16816(float* c, const uint32_t* a,
                                         const uint32_t* b) {
    asm volatile(
        "mma.sync.aligned.m16n8k16.row.col.f32.f16.f16.f32 "
        "{%0,%1,%2,%3}, {%4,%5,%6,%7}, {%8,%9}, {%0,%1,%2,%3};"
        : "+f"(c[0]), "+f"(c[1]), "+f"(c[2]), "+f"(c[3])
        : "r"(a[0]), "r"(a[1]), "r"(a[2]), "r"(a[3]), "r"(b[0]), "r"(b[1]));
}
__device__ __forceinline__ void cp_async16(uint32_t d, const void* g) {
    asm volatile("cp.async.cg.shared.global [%0], [%1], 16;"
                 :: "r"(d), "l"(g) : "memory");
}
#define CP_COMMIT() asm volatile("cp.async.commit_group;" ::: "memory")
#define CP_WAIT0()  asm volatile("cp.async.wait_group 0;" ::: "memory")

__device__ __forceinline__ uint32_t pack_h2(__half a, __half b) {
    __half2 h = __halves2half2(a, b);
    return *reinterpret_cast<uint32_t*>(&h);
}

// ---------------------------------------------------------------------------
// Kernel 1: split W -> g_Wh/g_Wl (same [k][n] layout)
// ---------------------------------------------------------------------------
__global__ void wsplit_kernel(const float* __restrict__ W) {
    const size_t i = ((size_t)blockIdx.x * 256 + threadIdx.x) * 4;
    const float4 v = *(const float4*)(W + i);
    const __half h0 = __float2half_rn(v.x), h1 = __float2half_rn(v.y);
    const __half h2 = __float2half_rn(v.z), h3 = __float2half_rn(v.w);
    const __half l0 = __float2half_rn(v.x - __half2float(h0));
    const __half l1 = __float2half_rn(v.y - __half2float(h1));
    const __half l2 = __float2half_rn(v.z - __half2float(h2));
    const __half l3 = __float2half_rn(v.w - __half2float(h3));
    *(uint2*)(g_Wh + i) = make_uint2(pack_h2(h0, h1), pack_h2(h2, h3));
    *(uint2*)(g_Wl + i) = make_uint2(pack_h2(l0, l1), pack_h2(l2, l3));
}

// ---------------------------------------------------------------------------
// Kernel 2: pipelined split-fp16 HMMA GEMM + fused Time2Vec epilogue
// 128 threads = 2x2 warps, each warp owns a 64x64 output tile.
// ---------------------------------------------------------------------------
__global__ __launch_bounds__(THREADS, 2)
void t2v_kernel(const float* __restrict__ x,
                const float* __restrict__ P,
                const float* __restrict__ w_p,
                const float* __restrict__ p_p,
                const float* __restrict__ sw_p,
                const float* __restrict__ cw_p,
                float* __restrict__ out) {
    extern __shared__ char smem[];
    const uint32_t sbase = smem_u32(smem);
    const int tid = threadIdx.x;
    const int lane = tid & 31, wid = tid >> 5;
    const int warp_m = wid & 1, warp_n = wid >> 1;     // 2 x 2 warps
    const int bm = blockIdx.x >> 3, bn = blockIdx.x & 7;
    const int m0 = bm * BM, n0 = bn * BN;

    const float w_s = __ldg(w_p), p_s = __ldg(p_p);
    const float sw = __ldg(sw_p), cw = __ldg(cw_p);

    // ---- per-lane ldmatrix geometry ----
    const uint32_t abase =
        (uint32_t)((warp_m * 64 + (lane & 15)) * 128 + (lane >> 4) * 16);
    const uint32_t bbase =
        (uint32_t)((warp_n * 32 + (lane & 15)) * 128 + (lane >> 4) * 16);
    const uint32_t lswz = ((uint32_t)lane & 7u) << 4;

    float acc[4][8][4];
#pragma unroll
    for (int mt = 0; mt < 4; mt++)
#pragma unroll
        for (int nt = 0; nt < 8; nt++)
#pragma unroll
            for (int q = 0; q < 4; q++) acc[mt][nt][q] = 0.0f;

    // ---- prologue: B(0) cp.async ----
    {
        const uint32_t sB = sbase + B_OFF;             // stage 0
#pragma unroll
        for (int i = 0; i < 8; i++) {
            const int idx = tid + i * 128;             // 0..1023
            const int hl = idx >> 9;                   // 0=hi, 1=lo
            const int r = (idx >> 3) & 63;             // nh*32 + k
            const int c = idx & 7;
            const int nh = r >> 5, kk = r & 31;
            const uint32_t dst = SWZ((hl * 64 + r) * 128 + c * 16);
            const __half* src =
                (hl ? g_Wl : g_Wh) + (size_t)kk * F + n0 + nh * 64 + c * 8;
            cp_async16(sB + dst, src);
        }
        CP_COMMIT();
    }

    // ---- mainloop ----
    for (int kc = 0; kc < NKC; kc++) {
        const int s = kc & 1;
        const uint32_t sA = sbase + s * STAGE_BYTES + A_OFF;
        const uint32_t sB = sbase + s * STAGE_BYTES + B_OFF;
        char* sAc = smem + s * STAGE_BYTES + A_OFF;
        const int k0 = kc * BK;

        // --- x(kc): batched LDG (latency overlaps B wait below) ---
        float4 v[8];
#pragma unroll
        for (int i = 0; i < 8; i++) {
            const int idx = tid + i * 128;             // 0..1023
            const int row = idx >> 3, c4 = idx & 7;
            v[i] = __ldg((const float4*)(x + (size_t)(m0 + row) * F + k0 +
                                         c4 * 4));
        }

        CP_WAIT0();   // B(kc) landed

        // --- convert x -> Ah|Al rows; bn==0 CTAs also emit linear half ---
#pragma unroll
        for (int i = 0; i < 8; i++) {
            const int idx = tid + i * 128;
            const int row = idx >> 3, c4 = idx & 7;
            const float4 vv = v[i];
            const __half h0 = __float2half_rn(vv.x), h1 = __float2half_rn(vv.y);
            const __half h2 = __float2half_rn(vv.z), h3 = __float2half_rn(vv.w);
            const __half l0 = __float2half_rn(vv.x - __half2float(h0));
            const __half l1 = __float2half_rn(vv.y - __half2float(h1));
            const __half l2 = __float2half_rn(vv.z - __half2float(h2));
            const __half l3 = __float2half_rn(vv.w - __half2float(h3));
            const uint32_t base = (uint32_t)(row * 128 + c4 * 8);
            const uint32_t rswz = ((uint32_t)row & 7u) << 4;
            *(uint32_t*)(sAc + (base ^ rswz)) = pack_h2(h0, h1);
            *(uint32_t*)(sAc + ((base + 4) ^ rswz)) = pack_h2(h2, h3);
            *(uint32_t*)(sAc + ((base + 64) ^ rswz)) = pack_h2(l0, l1);
            *(uint32_t*)(sAc + ((base + 68) ^ rswz)) = pack_h2(l2, l3);
            if (bn == 0) {
                float4 o;
                o.x = w_s * vv.x + p_s; o.y = w_s * vv.y + p_s;
                o.z = w_s * vv.z + p_s; o.w = w_s * vv.w + p_s;
                *(float4*)(out + (size_t)(m0 + row) * (2 * F) + k0 + c4 * 4) = o;
            }
        }
        __syncthreads();   // A+B of chunk kc visible; prior-chunk reads done

        if (kc < NKC - 1) {
            // prefetch B(kc+1) under the MMA shadow
            const uint32_t sBn = sbase + (s ^ 1) * STAGE_BYTES + B_OFF;
            const int k1 = k0 + BK;
#pragma unroll
            for (int i = 0; i < 8; i++) {
                const int idx = tid + i * 128;
                const int hl = idx >> 9;
                const int r = (idx >> 3) & 63;
                const int c = idx & 7;
                const int nh = r >> 5, kk = r & 31;
                const uint32_t dst = SWZ((hl * 64 + r) * 128 + c * 16);
                const __half* src = (hl ? g_Wl : g_Wh) + (size_t)(k1 + kk) * F +
                                    n0 + nh * 64 + c * 8;
                cp_async16(sBn + dst, src);
            }
            CP_COMMIT();
        }

        // ---- MMAs over stage s ----
#pragma unroll
        for (int ks = 0; ks < 2; ks++) {
            uint32_t ah[4][4], al[4][4], bh[8][2], bl[8][2];
#pragma unroll
            for (int mt = 0; mt < 4; mt++) {
                ldsm_x4(ah[mt], sA + ((abase + mt * 2048 + ks * 32) ^ lswz));
                ldsm_x4(al[mt],
                        sA + ((abase + mt * 2048 + 64 + ks * 32) ^ lswz));
            }
#pragma unroll
            for (int np = 0; np < 4; np++) {
                uint32_t t4[4];
                ldsm_x4_t(t4, sB + ((bbase + ks * 2048 + np * 32) ^ lswz));
                bh[np * 2][0] = t4[0]; bh[np * 2][1] = t4[1];
                bh[np * 2 + 1][0] = t4[2]; bh[np * 2 + 1][1] = t4[3];
                ldsm_x4_t(t4,
                          sB + ((bbase + 8192 + ks * 2048 + np * 32) ^ lswz));
                bl[np * 2][0] = t4[0]; bl[np * 2][1] = t4[1];
                bl[np * 2 + 1][0] = t4[2]; bl[np * 2 + 1][1] = t4[3];
            }
#pragma unroll
            for (int mt = 0; mt < 4; mt++)
#pragma unroll
                for (int nt = 0; nt < 8; nt++) {
                    mma16816(acc[mt][nt], ah[mt], bh[nt]);
                    mma16816(acc[mt][nt], ah[mt], bl[nt]);
                    mma16816(acc[mt][nt], al[mt], bh[nt]);
                }
        }
    }

    // ---- epilogue: z = acc + P[n]; periodic = sw*sin(z)+cw*cos(z) ----
    const int gid = lane >> 2, tig = lane & 3;
#pragma unroll
    for (int nt = 0; nt < 8; nt++) {
        const int n = n0 + warp_n * 64 + nt * 8 + tig * 2;
        const float P0 = __ldg(P + n), P1 = __ldg(P + n + 1);
#pragma unroll
        for (int mt = 0; mt < 4; mt++) {
            const int mrow = m0 + warp_m * 64 + mt * 16 + gid;
            float s0, c0, s1, c1;
            __sincosf(acc[mt][nt][0] + P0, &s0, &c0);
            __sincosf(acc[mt][nt][1] + P1, &s1, &c1);
            *(float2*)(out + (size_t)mrow * (2 * F) + F + n) =
                make_float2(sw * s0 + cw * c0, sw * s1 + cw * c1);
            __sincosf(acc[mt][nt][2] + P0, &s0, &c0);
            __sincosf(acc[mt][nt][3] + P1, &s1, &c1);
            *(float2*)(out + (size_t)(mrow + 8) * (2 * F) + F + n) =
                make_float2(sw * s0 + cw * c0, sw * s1 + cw * c1);
        }
    }
}

// ---------------------------------------------------------------------------
extern "C" void kernel_launch(void* const* d_in, const int* in_sizes, int n_in,
                              void* d_out, int out_size) {
    (void)in_sizes; (void)n_in; (void)out_size;
    const float* x  = (const float*)d_in[0];
    const float* W  = (const float*)d_in[1];
    const float* P  = (const float*)d_in[2];
    const float* w  = (const float*)d_in[3];
    const float* p  = (const float*)d_in[4];
    const float* sw = (const float*)d_in[5];
    const float* cw = (const float*)d_in[6];
    float* out = (float*)d_out;

    cudaFuncSetAttribute(t2v_kernel,
                         cudaFuncAttributeMaxDynamicSharedMemorySize,
                         SMEM_TOTAL);

    wsplit_kernel<<<(F * F) / (256 * 4), 256>>>(W);
    t2v_kernel<<<(BATCH / BM) * (F / BN), THREADS, SMEM_TOTAL>>>(
        x, P, w, p, sw, cw, out);
}

// round 13
// speedup vs baseline: 1.2396x; 1.0053x over previous
#include <cuda_runtime.h>
#include <cuda_fp16.h>
#include <cstdint>
#include <math.h>

// ============================================================================
// Time2Vec:  out[:, :1024] = w*x + p
//            out[:, 1024:] = sine_w*sin(x@W + P) + cosine_w*cos(x@W + P)
// GEMM via mma.sync.m16n8k16 fp16 2-way-split (3 MMAs, fp32 accum).
// R13 == R12 resubmit (infra failure): epilogue sw*sin(z)+cw*cos(z)
//      -> R*sin(z+phi), halving MUFU ops (R11 was MUFU-bound at ~930us).
// ============================================================================

#define F       1024
#define BATCH   65536
#define BM      128
#define BN      128
#define BK      32
#define NKC     (F / BK)            // 32
#define THREADS 128

#define STAGE_BYTES 32768           // A: 16KB (128 rows x 128B), B: 16KB
#define A_OFF       0
#define B_OFF       16384
#define SMEM_TOTAL  (2 * STAGE_BYTES)   // 64 KB -> 2 CTAs/SM

// Pre-split W (row-major [k][n], fp16 hi/lo)
__device__ __half g_Wh[(size_t)F * F];
__device__ __half g_Wl[(size_t)F * F];

// ---------------------------------------------------------------------------
// helpers
// ---------------------------------------------------------------------------
__device__ __forceinline__ uint32_t smem_u32(const void* p) {
    uint32_t a;
    asm("{ .reg .u64 t; cvta.to.shared.u64 t, %1; cvt.u32.u64 %0, t; }"
        : "=r"(a) : "l"(p));
    return a;
}

#define SWZ(o) ((uint32_t)(o) ^ ((((uint32_t)(o)) >> 3) & 0x70))

__device__ __forceinline__ void ldsm_x4(uint32_t* r, uint32_t addr) {
    asm volatile(
        "ldmatrix.sync.aligned.m8n8.x4.shared.b16 {%0,%1,%2,%3}, [%4];"
        : "=r"(r[0]), "=r"(r[1]), "=r"(r[2]), "=r"(r[3]) : "r"(addr));
}
__device__ __forceinline__ void ldsm_x4_t(uint32_t* r, uint32_t addr) {
    asm volatile(
        "ldmatrix.sync.aligned.m8n8.x4.trans.shared.b16 {%0,%1,%2,%3}, [%4];"
        : "=r"(r[0]), "=r"(r[1]), "=r"(r[2]), "=r"(r[3]) : "r"(addr));
}
__device__ __forceinline__ void mma16816(float* c, const uint32_t* a,
                                         const uint32_t* b) {
    asm volatile(
        "mma.sync.aligned.m16n8k16.row.col.f32.f16.f16.f32 "
        "{%0,%1,%2,%3}, {%4,%5,%6,%7}, {%8,%9}, {%0,%1,%2,%3};"
        : "+f"(c[0]), "+f"(c[1]), "+f"(c[2]), "+f"(c[3])
        : "r"(a[0]), "r"(a[1]), "r"(a[2]), "r"(a[3]), "r"(b[0]), "r"(b[1]));
}
__device__ __forceinline__ void cp_async16(uint32_t d, const void* g) {
    asm volatile("cp.async.cg.shared.global [%0], [%1], 16;"
                 :: "r"(d), "l"(g) : "memory");
}
#define CP_COMMIT() asm volatile("cp.async.commit_group;" ::: "memory")
#define CP_WAIT0()  asm volatile("cp.async.wait_group 0;" ::: "memory")

__device__ __forceinline__ uint32_t pack_h2(__half a, __half b) {
    __half2 h = __halves2half2(a, b);
    return *reinterpret_cast<uint32_t*>(&h);
}

// ---------------------------------------------------------------------------
// Kernel 1: split W -> g_Wh/g_Wl (same [k][n] layout)
// ---------------------------------------------------------------------------
__global__ void wsplit_kernel(const float* __restrict__ W) {
    const size_t i = ((size_t)blockIdx.x * 256 + threadIdx.x) * 4;
    const float4 v = *(const float4*)(W + i);
    const __half h0 = __float2half_rn(v.x), h1 = __float2half_rn(v.y);
    const __half h2 = __float2half_rn(v.z), h3 = __float2half_rn(v.w);
    const __half l0 = __float2half_rn(v.x - __half2float(h0));
    const __half l1 = __float2half_rn(v.y - __half2float(h1));
    const __half l2 = __float2half_rn(v.z - __half2float(h2));
    const __half l3 = __float2half_rn(v.w - __half2float(h3));
    *(uint2*)(g_Wh + i) = make_uint2(pack_h2(h0, h1), pack_h2(h2, h3));
    *(uint2*)(g_Wl + i) = make_uint2(pack_h2(l0, l1), pack_h2(l2, l3));
}

// ---------------------------------------------------------------------------
// Kernel 2: pipelined split-fp16 HMMA GEMM + fused Time2Vec epilogue
// 128 threads = 2x2 warps, each warp owns a 64x64 output tile.
// ---------------------------------------------------------------------------
__global__ __launch_bounds__(THREADS, 2)
void t2v_kernel(const float* __restrict__ x,
                const float* __restrict__ P,
                const float* __restrict__ w_p,
                const float* __restrict__ p_p,
                const float* __restrict__ sw_p,
                const float* __restrict__ cw_p,
                float* __restrict__ out) {
    extern __shared__ char smem[];
    const uint32_t sbase = smem_u32(smem);
    const int tid = threadIdx.x;
    const int lane = tid & 31, wid = tid >> 5;
    const int warp_m = wid & 1, warp_n = wid >> 1;     // 2 x 2 warps
    const int bm = blockIdx.x >> 3, bn = blockIdx.x & 7;
    const int m0 = bm * BM, n0 = bn * BN;

    const float w_s = __ldg(w_p), p_s = __ldg(p_p);
    const float sw = __ldg(sw_p), cw = __ldg(cw_p);
    // sw*sin(z) + cw*cos(z) = R*sin(z + phi):  one MUFU.SIN per element
    const float Ramp = sqrtf(sw * sw + cw * cw);
    const float phi  = atan2f(cw, sw);

    // ---- per-lane ldmatrix geometry ----
    const uint32_t abase =
        (uint32_t)((warp_m * 64 + (lane & 15)) * 128 + (lane >> 4) * 16);
    const uint32_t bbase =
        (uint32_t)((warp_n * 32 + (lane & 15)) * 128 + (lane >> 4) * 16);
    const uint32_t lswz = ((uint32_t)lane & 7u) << 4;

    float acc[4][8][4];
#pragma unroll
    for (int mt = 0; mt < 4; mt++)
#pragma unroll
        for (int nt = 0; nt < 8; nt++)
#pragma unroll
            for (int q = 0; q < 4; q++) acc[mt][nt][q] = 0.0f;

    // ---- prologue: B(0) cp.async ----
    {
        const uint32_t sB = sbase + B_OFF;             // stage 0
#pragma unroll
        for (int i = 0; i < 8; i++) {
            const int idx = tid + i * 128;             // 0..1023
            const int hl = idx >> 9;                   // 0=hi, 1=lo
            const int r = (idx >> 3) & 63;             // nh*32 + k
            const int c = idx & 7;
            const int nh = r >> 5, kk = r & 31;
            const uint32_t dst = SWZ((hl * 64 + r) * 128 + c * 16);
            const __half* src =
                (hl ? g_Wl : g_Wh) + (size_t)kk * F + n0 + nh * 64 + c * 8;
            cp_async16(sB + dst, src);
        }
        CP_COMMIT();
    }

    // ---- mainloop ----
    for (int kc = 0; kc < NKC; kc++) {
        const int s = kc & 1;
        const uint32_t sA = sbase + s * STAGE_BYTES + A_OFF;
        const uint32_t sB = sbase + s * STAGE_BYTES + B_OFF;
        char* sAc = smem + s * STAGE_BYTES + A_OFF;
        const int k0 = kc * BK;

        // --- x(kc): batched LDG (latency overlaps B wait below) ---
        float4 v[8];
#pragma unroll
        for (int i = 0; i < 8; i++) {
            const int idx = tid + i * 128;             // 0..1023
            const int row = idx >> 3, c4 = idx & 7;
            v[i] = __ldg((const float4*)(x + (size_t)(m0 + row) * F + k0 +
                                         c4 * 4));
        }

        CP_WAIT0();   // B(kc) landed

        // --- convert x -> Ah|Al rows; bn==0 CTAs also emit linear half ---
#pragma unroll
        for (int i = 0; i < 8; i++) {
            const int idx = tid + i * 128;
            const int row = idx >> 3, c4 = idx & 7;
            const float4 vv = v[i];
            const __half h0 = __float2half_rn(vv.x), h1 = __float2half_rn(vv.y);
            const __half h2 = __float2half_rn(vv.z), h3 = __float2half_rn(vv.w);
            const __half l0 = __float2half_rn(vv.x - __half2float(h0));
            const __half l1 = __float2half_rn(vv.y - __half2float(h1));
            const __half l2 = __float2half_rn(vv.z - __half2float(h2));
            const __half l3 = __float2half_rn(vv.w - __half2float(h3));
            const uint32_t base = (uint32_t)(row * 128 + c4 * 8);
            const uint32_t rswz = ((uint32_t)row & 7u) << 4;
            *(uint32_t*)(sAc + (base ^ rswz)) = pack_h2(h0, h1);
            *(uint32_t*)(sAc + ((base + 4) ^ rswz)) = pack_h2(h2, h3);
            *(uint32_t*)(sAc + ((base + 64) ^ rswz)) = pack_h2(l0, l1);
            *(uint32_t*)(sAc + ((base + 68) ^ rswz)) = pack_h2(l2, l3);
            if (bn == 0) {
                float4 o;
                o.x = w_s * vv.x + p_s; o.y = w_s * vv.y + p_s;
                o.z = w_s * vv.z + p_s; o.w = w_s * vv.w + p_s;
                *(float4*)(out + (size_t)(m0 + row) * (2 * F) + k0 + c4 * 4) = o;
            }
        }
        __syncthreads();   // A+B of chunk kc visible; prior-chunk reads done

        if (kc < NKC - 1) {
            // prefetch B(kc+1) under the MMA shadow
            const uint32_t sBn = sbase + (s ^ 1) * STAGE_BYTES + B_OFF;
            const int k1 = k0 + BK;
#pragma unroll
            for (int i = 0; i < 8; i++) {
                const int idx = tid + i * 128;
                const int hl = idx >> 9;
                const int r = (idx >> 3) & 63;
                const int c = idx & 7;
                const int nh = r >> 5, kk = r & 31;
                const uint32_t dst = SWZ((hl * 64 + r) * 128 + c * 16);
                const __half* src = (hl ? g_Wl : g_Wh) + (size_t)(k1 + kk) * F +
                                    n0 + nh * 64 + c * 8;
                cp_async16(sBn + dst, src);
            }
            CP_COMMIT();
        }

        // ---- MMAs over stage s ----
#pragma unroll
        for (int ks = 0; ks < 2; ks++) {
            uint32_t ah[4][4], al[4][4], bh[8][2], bl[8][2];
#pragma unroll
            for (int mt = 0; mt < 4; mt++) {
                ldsm_x4(ah[mt], sA + ((abase + mt * 2048 + ks * 32) ^ lswz));
                ldsm_x4(al[mt],
                        sA + ((abase + mt * 2048 + 64 + ks * 32) ^ lswz));
            }
#pragma unroll
            for (int np = 0; np < 4; np++) {
                uint32_t t4[4];
                ldsm_x4_t(t4, sB + ((bbase + ks * 2048 + np * 32) ^ lswz));
                bh[np * 2][0] = t4[0]; bh[np * 2][1] = t4[1];
                bh[np * 2 + 1][0] = t4[2]; bh[np * 2 + 1][1] = t4[3];
                ldsm_x4_t(t4,
                          sB + ((bbase + 8192 + ks * 2048 + np * 32) ^ lswz));
                bl[np * 2][0] = t4[0]; bl[np * 2][1] = t4[1];
                bl[np * 2 + 1][0] = t4[2]; bl[np * 2 + 1][1] = t4[3];
            }
#pragma unroll
            for (int mt = 0; mt < 4; mt++)
#pragma unroll
                for (int nt = 0; nt < 8; nt++) {
                    mma16816(acc[mt][nt], ah[mt], bh[nt]);
                    mma16816(acc[mt][nt], ah[mt], bl[nt]);
                    mma16816(acc[mt][nt], al[mt], bh[nt]);
                }
        }
    }

    // ---- epilogue: z = acc + P[n]; periodic = R*sin(z + phi) ----
    const int gid = lane >> 2, tig = lane & 3;
#pragma unroll
    for (int nt = 0; nt < 8; nt++) {
        const int n = n0 + warp_n * 64 + nt * 8 + tig * 2;
        const float P0 = __ldg(P + n) + phi, P1 = __ldg(P + n + 1) + phi;
#pragma unroll
        for (int mt = 0; mt < 4; mt++) {
            const int mrow = m0 + warp_m * 64 + mt * 16 + gid;
            *(float2*)(out + (size_t)mrow * (2 * F) + F + n) =
                make_float2(Ramp * __sinf(acc[mt][nt][0] + P0),
                            Ramp * __sinf(acc[mt][nt][1] + P1));
            *(float2*)(out + (size_t)(mrow + 8) * (2 * F) + F + n) =
                make_float2(Ramp * __sinf(acc[mt][nt][2] + P0),
                            Ramp * __sinf(acc[mt][nt][3] + P1));
        }
    }
}

// ---------------------------------------------------------------------------
extern "C" void kernel_launch(void* const* d_in, const int* in_sizes, int n_in,
                              void* d_out, int out_size) {
    (void)in_sizes; (void)n_in; (void)out_size;
    const float* x  = (const float*)d_in[0];
    const float* W  = (const float*)d_in[1];
    const float* P  = (const float*)d_in[2];
    const float* w  = (const float*)d_in[3];
    const float* p  = (const float*)d_in[4];
    const float* sw = (const float*)d_in[5];
    const float* cw = (const float*)d_in[6];
    float* out = (float*)d_out;

    cudaFuncSetAttribute(t2v_kernel,
                         cudaFuncAttributeMaxDynamicSharedMemorySize,
                         SMEM_TOTAL);

    wsplit_kernel<<<(F * F) / (256 * 4), 256>>>(W);
    t2v_kernel<<<(BATCH / BM) * (F / BN), THREADS, SMEM_TOTAL>>>(
        x, P, w, p, sw, cw, out);
}